// round 1
// baseline (speedup 1.0000x reference)
#include <cuda_runtime.h>
#include <cuda_bf16.h>

// Segment-mean: out[s, :] = mean over nodes i with label[i]==s of node_input[i, :]
// N=200000, DIM=480, NSEG=4096. Strategy: build CSR (hist -> scan -> scatter),
// then gather-reduce one CTA per segment (HBM-bound streaming pass).

#define N_MAX   262144
#define S_MAX   4096

__device__ int g_counts[S_MAX];
__device__ int g_offsets[S_MAX + 1];
__device__ int g_cursor[S_MAX];
__device__ int g_order[N_MAX];
__device__ int g_lab32;   // 1 => labels are int32, 0 => int64

// ---------------------------------------------------------------- init
__global__ void k_init(int nseg) {
    int i = blockIdx.x * blockDim.x + threadIdx.x;
    if (i < nseg) g_counts[i] = 0;
    if (i == 0) g_lab32 = 0;
}

// ---------------------------------------------------------------- dtype detect
// Read the label buffer as int64 over n/2 elements (covers the full buffer in
// either layout without OOB). If labels are really int32, an int64 read packs
// two labels and the high word is almost surely nonzero -> out of [0,nseg).
__global__ void k_detect(const long long* p, int n, int nseg) {
    int half = n >> 1;
    int bad = 0;
    for (int i = blockIdx.x * blockDim.x + threadIdx.x; i < half;
         i += gridDim.x * blockDim.x) {
        long long v = p[i];
        if (v < 0 || v >= (long long)nseg) bad = 1;
    }
    if (__syncthreads_or(bad)) {
        if (threadIdx.x == 0) g_lab32 = 1;
    }
}

__device__ __forceinline__ int load_label(const void* p, int i, int lab32) {
    if (lab32) return ((const int*)p)[i];
    return (int)(((const long long*)p)[i]);
}

// ---------------------------------------------------------------- histogram
__global__ void k_hist(const void* labels, int n, int nseg) {
    __shared__ int h[S_MAX];
    int lab32 = g_lab32;
    for (int i = threadIdx.x; i < nseg; i += blockDim.x) h[i] = 0;
    __syncthreads();
    for (int i = blockIdx.x * blockDim.x + threadIdx.x; i < n;
         i += gridDim.x * blockDim.x) {
        int lab = load_label(labels, i, lab32);
        atomicAdd(&h[lab], 1);
    }
    __syncthreads();
    for (int i = threadIdx.x; i < nseg; i += blockDim.x) {
        int v = h[i];
        if (v) atomicAdd(&g_counts[i], v);
    }
}

// ---------------------------------------------------------------- scan (nseg<=4096, 1024 thr)
__global__ void k_scan(int nseg) {
    __shared__ int ts[1024];
    int t = threadIdx.x;
    int base = t * 4;
    int c0 = 0, c1 = 0, c2 = 0, c3 = 0;
    if (base + 3 < nseg) {
        c0 = g_counts[base];     c1 = g_counts[base + 1];
        c2 = g_counts[base + 2]; c3 = g_counts[base + 3];
    } else {
        if (base     < nseg) c0 = g_counts[base];
        if (base + 1 < nseg) c1 = g_counts[base + 1];
        if (base + 2 < nseg) c2 = g_counts[base + 2];
    }
    ts[t] = c0 + c1 + c2 + c3;
    __syncthreads();
    for (int off = 1; off < 1024; off <<= 1) {
        int v = ts[t];
        int add = (t >= off) ? ts[t - off] : 0;
        __syncthreads();
        ts[t] = v + add;
        __syncthreads();
    }
    int excl = (t == 0) ? 0 : ts[t - 1];
    if (base < nseg)     { g_offsets[base]     = excl;               g_cursor[base]     = excl; }
    excl += c0;
    if (base + 1 < nseg) { g_offsets[base + 1] = excl;               g_cursor[base + 1] = excl; }
    excl += c1;
    if (base + 2 < nseg) { g_offsets[base + 2] = excl;               g_cursor[base + 2] = excl; }
    excl += c2;
    if (base + 3 < nseg) { g_offsets[base + 3] = excl;               g_cursor[base + 3] = excl; }
    if (t == 1023) g_offsets[nseg] = ts[1023];
}

// ---------------------------------------------------------------- scatter node ids
__global__ void k_scatter(const void* labels, int n) {
    int lab32 = g_lab32;
    for (int i = blockIdx.x * blockDim.x + threadIdx.x; i < n;
         i += gridDim.x * blockDim.x) {
        int lab = load_label(labels, i, lab32);
        int pos = atomicAdd(&g_cursor[lab], 1);
        g_order[pos] = i;
    }
}

// ---------------------------------------------------------------- gather-reduce
// One CTA per segment. dim4 = DIM/4 = 120 float4 columns; thread t owns column t.
__global__ __launch_bounds__(128, 16)
void k_reduce(const float4* __restrict__ in, float* __restrict__ out, int dim4) {
    int s = blockIdx.x;
    int t = threadIdx.x;
    if (t >= dim4) return;

    int start = g_offsets[s];
    int end   = g_offsets[s + 1];
    int cnt   = end - start;

    float4 a0 = make_float4(0.f, 0.f, 0.f, 0.f);
    float4 a1 = a0, a2 = a0, a3 = a0;

    int j = start;
    for (; j + 4 <= end; j += 4) {
        int i0 = __ldg(&g_order[j]);
        int i1 = __ldg(&g_order[j + 1]);
        int i2 = __ldg(&g_order[j + 2]);
        int i3 = __ldg(&g_order[j + 3]);
        float4 v0 = __ldg(&in[(long long)i0 * dim4 + t]);
        float4 v1 = __ldg(&in[(long long)i1 * dim4 + t]);
        float4 v2 = __ldg(&in[(long long)i2 * dim4 + t]);
        float4 v3 = __ldg(&in[(long long)i3 * dim4 + t]);
        a0.x += v0.x; a0.y += v0.y; a0.z += v0.z; a0.w += v0.w;
        a1.x += v1.x; a1.y += v1.y; a1.z += v1.z; a1.w += v1.w;
        a2.x += v2.x; a2.y += v2.y; a2.z += v2.z; a2.w += v2.w;
        a3.x += v3.x; a3.y += v3.y; a3.z += v3.z; a3.w += v3.w;
    }
    for (; j < end; j++) {
        int i0 = __ldg(&g_order[j]);
        float4 v0 = __ldg(&in[(long long)i0 * dim4 + t]);
        a0.x += v0.x; a0.y += v0.y; a0.z += v0.z; a0.w += v0.w;
    }

    float4 acc;
    acc.x = (a0.x + a1.x) + (a2.x + a3.x);
    acc.y = (a0.y + a1.y) + (a2.y + a3.y);
    acc.z = (a0.z + a1.z) + (a2.z + a3.z);
    acc.w = (a0.w + a1.w) + (a2.w + a3.w);

    float inv = 1.0f / (float)(cnt > 0 ? cnt : 1);
    acc.x *= inv; acc.y *= inv; acc.z *= inv; acc.w *= inv;

    ((float4*)out)[(long long)s * dim4 + t] = acc;
}

// ---------------------------------------------------------------- launch
extern "C" void kernel_launch(void* const* d_in, const int* in_sizes, int n_in,
                              void* d_out, int out_size) {
    const float* node_input = (const float*)d_in[0];
    const void*  labels     = d_in[1];

    int n    = in_sizes[1];
    int dim  = in_sizes[0] / n;          // 480
    int nseg = out_size / dim;           // 4096
    int dim4 = dim / 4;                  // 120

    if (n > N_MAX || nseg > S_MAX) return;

    k_init<<<(nseg + 255) / 256, 256>>>(nseg);
    k_detect<<<128, 256>>>((const long long*)labels, n, nseg);
    k_hist<<<148, 256>>>(labels, n, nseg);
    k_scan<<<1, 1024>>>(nseg);
    k_scatter<<<200, 256>>>(labels, n);
    k_reduce<<<nseg, 128>>>((const float4*)node_input, (float*)d_out, dim4);
}